// round 1
// baseline (speedup 1.0000x reference)
#include <cuda_runtime.h>

#define ALPHA 0.2f
constexpr int Bn = 64, Kn = 100, Fn = 128, En = 200;
constexpr int EPAD = 204;           // E padded to multiple of 4 (vector loads)
constexpr int ROWS = Bn * Kn;       // 6400

// Scratch (no allocations allowed): projections
__device__ float g_UL[ROWS * En];   // left proj + bias b folded in
__device__ float g_R[ROWS * En];    // right proj

// ---------------------------------------------------------------------------
// Kernel 1: projection GEMM.  X:(6400,128) @ [W_top | W_bot]:(128,400)
// col n < 200 -> UL (+= b[n]); n in [200,400) -> R[n-200]
// ---------------------------------------------------------------------------
__global__ void proj_kernel(const float* __restrict__ x,
                            const float* __restrict__ W,
                            const float* __restrict__ bvec) {
    extern __shared__ float sm[];
    float(*xs)[132] = (float(*)[132])sm;               // 64 x 132 (padded)
    float(*ws)[64]  = (float(*)[64])(sm + 64 * 132);   // 128 x 64

    const int row0 = blockIdx.y * 64;
    const int n0   = blockIdx.x * 64;
    const int tid  = threadIdx.x;

    for (int idx = tid; idx < 64 * 128; idx += 256) {
        int r = idx >> 7, f = idx & 127;
        xs[r][f] = x[(row0 + r) * Fn + f];
    }
    for (int idx = tid; idx < 128 * 64; idx += 256) {
        int f = idx >> 6, c = idx & 63;
        int n = n0 + c;
        float v = 0.f;
        if (n < En)            v = W[f * En + n];
        else if (n < 2 * En)   v = W[(Fn + f) * En + (n - En)];
        ws[f][c] = v;
    }
    __syncthreads();

    const int tx = tid & 15, ty = tid >> 4;
    float acc[4][4] = {};
#pragma unroll 4
    for (int f = 0; f < 128; f++) {
        float4 wv = *(const float4*)&ws[f][4 * tx];
        float xr[4];
#pragma unroll
        for (int r = 0; r < 4; r++) xr[r] = xs[4 * ty + r][f];
#pragma unroll
        for (int r = 0; r < 4; r++) {
            acc[r][0] = fmaf(xr[r], wv.x, acc[r][0]);
            acc[r][1] = fmaf(xr[r], wv.y, acc[r][1]);
            acc[r][2] = fmaf(xr[r], wv.z, acc[r][2]);
            acc[r][3] = fmaf(xr[r], wv.w, acc[r][3]);
        }
    }
#pragma unroll
    for (int r = 0; r < 4; r++) {
        int row = row0 + 4 * ty + r;
#pragma unroll
        for (int c = 0; c < 4; c++) {
            int n = n0 + 4 * tx + c;
            if (n < En)          g_UL[row * En + n] = acc[r][c] + bvec[n];
            else if (n < 2 * En) g_R[row * En + (n - En)] = acc[r][c];
        }
    }
}

// ---------------------------------------------------------------------------
// Kernel 2: fused pairwise-leaky attention + softmax + attn@x + sigmoid.
// Block = (b, tile of 16 i-rows).  Warp w owns i = i0+w. Lanes own j.
// e_ij = alpha*(ua_i + ra_j) + (1-alpha)*sum_e max(u_i+R_j,0)*a_e + bias_ij
// ---------------------------------------------------------------------------
__global__ __launch_bounds__(512, 1)
void attn_kernel(const float* __restrict__ x,
                 const float* __restrict__ avec,
                 const float* __restrict__ bias,
                 float* __restrict__ out) {
    extern __shared__ float sm[];
    float* R_sm  = sm;                   // 128 * 204  (rows >=100 zero)
    float* xs    = R_sm + 128 * EPAD;    // 100 * 128
    float* u_sm  = xs + Kn * Fn;         // 16 * 204
    float* a_sm  = u_sm + 16 * EPAD;     // 204
    float* a1_sm = a_sm + EPAD;          // 204 : (1-alpha)*a
    float* ra_sm = a1_sm + EPAD;         // 128 : alpha * (R_j . a)
    float* prow  = ra_sm + 128;          // 16 * 128 : unnormalized softmax

    const int b   = blockIdx.x;
    const int i0  = blockIdx.y * 16;
    const int tid = threadIdx.x;
    const int wid = tid >> 5, lane = tid & 31;

    // ---- Phase 1: stage everything into smem (zero-padded) ----
    for (int idx = tid; idx < 128 * EPAD; idx += 512) {
        int j = idx / EPAD, e = idx - j * EPAD;
        R_sm[idx] = (j < Kn && e < En) ? g_R[(b * Kn + j) * En + e] : 0.f;
    }
    for (int idx = tid; idx < Kn * Fn; idx += 512)
        xs[idx] = x[b * Kn * Fn + idx];
    for (int idx = tid; idx < 16 * EPAD; idx += 512) {
        int ii = idx / EPAD, e = idx - ii * EPAD;
        int i = i0 + ii;
        u_sm[idx] = (i < Kn && e < En) ? g_UL[(b * Kn + i) * En + e] : 0.f;
    }
    for (int e = tid; e < EPAD; e += 512) {
        float av = (e < En) ? avec[e] : 0.f;
        a_sm[e]  = av;
        a1_sm[e] = (1.0f - ALPHA) * av;
    }
    __syncthreads();

    // ---- Phase 2: ra_j = alpha * (R_j . a), 8 rows per warp ----
#pragma unroll
    for (int r = 0; r < 8; r++) {
        int j = wid * 8 + r;
        float s = 0.f;
        for (int e = lane; e < EPAD; e += 32)
            s = fmaf(R_sm[j * EPAD + e], a_sm[e], s);
#pragma unroll
        for (int o = 16; o; o >>= 1) s += __shfl_xor_sync(0xffffffffu, s, o);
        if (lane == 0) ra_sm[j] = ALPHA * s;
    }
    // ua_i = alpha * (u_i . a) for this warp's row
    float aua;
    {
        float s = 0.f;
        for (int e = lane; e < EPAD; e += 32)
            s = fmaf(u_sm[wid * EPAD + e], a_sm[e], s);
#pragma unroll
        for (int o = 16; o; o >>= 1) s += __shfl_xor_sync(0xffffffffu, s, o);
        aua = ALPHA * s;
    }
    __syncthreads();

    // ---- Phase 3: per-warp row i ----
    const int i = i0 + wid;
    if (i < Kn) {
        // bias prefetch (4 j's per lane)
        float bias4[4];
#pragma unroll
        for (int jb = 0; jb < 4; jb++) {
            int j = jb * 32 + lane;
            bias4[jb] = (j < Kn) ? bias[i * Kn + j] : 0.f;
        }

        float s0 = 0.f, s1 = 0.f, s2 = 0.f, s3 = 0.f;
        const float* r0p = R_sm + (0 * 32 + lane) * EPAD;
        const float* r1p = R_sm + (1 * 32 + lane) * EPAD;
        const float* r2p = R_sm + (2 * 32 + lane) * EPAD;
        const float* r3p = R_sm + (3 * 32 + lane) * EPAD;
        const float* up  = u_sm + wid * EPAD;

#pragma unroll 3
        for (int ec = 0; ec < EPAD / 4; ec++) {
            float4 u4 = *(const float4*)(up + 4 * ec);
            float4 a4 = *(const float4*)(a1_sm + 4 * ec);
            float4 r4;
            r4 = *(const float4*)(r0p + 4 * ec);
            s0 = fmaf(fmaxf(u4.x + r4.x, 0.f), a4.x, s0);
            s0 = fmaf(fmaxf(u4.y + r4.y, 0.f), a4.y, s0);
            s0 = fmaf(fmaxf(u4.z + r4.z, 0.f), a4.z, s0);
            s0 = fmaf(fmaxf(u4.w + r4.w, 0.f), a4.w, s0);
            r4 = *(const float4*)(r1p + 4 * ec);
            s1 = fmaf(fmaxf(u4.x + r4.x, 0.f), a4.x, s1);
            s1 = fmaf(fmaxf(u4.y + r4.y, 0.f), a4.y, s1);
            s1 = fmaf(fmaxf(u4.z + r4.z, 0.f), a4.z, s1);
            s1 = fmaf(fmaxf(u4.w + r4.w, 0.f), a4.w, s1);
            r4 = *(const float4*)(r2p + 4 * ec);
            s2 = fmaf(fmaxf(u4.x + r4.x, 0.f), a4.x, s2);
            s2 = fmaf(fmaxf(u4.y + r4.y, 0.f), a4.y, s2);
            s2 = fmaf(fmaxf(u4.z + r4.z, 0.f), a4.z, s2);
            s2 = fmaf(fmaxf(u4.w + r4.w, 0.f), a4.w, s2);
            r4 = *(const float4*)(r3p + 4 * ec);
            s3 = fmaf(fmaxf(u4.x + r4.x, 0.f), a4.x, s3);
            s3 = fmaf(fmaxf(u4.y + r4.y, 0.f), a4.y, s3);
            s3 = fmaf(fmaxf(u4.z + r4.z, 0.f), a4.z, s3);
            s3 = fmaf(fmaxf(u4.w + r4.w, 0.f), a4.w, s3);
        }

        float sv[4] = {s0, s1, s2, s3};
        float el[4];
        float m = -1e30f;
#pragma unroll
        for (int jb = 0; jb < 4; jb++) {
            int j = jb * 32 + lane;
            el[jb] = (j < Kn) ? (aua + ra_sm[j] + sv[jb] + bias4[jb]) : -1e30f;
            m = fmaxf(m, el[jb]);
        }
#pragma unroll
        for (int o = 16; o; o >>= 1) m = fmaxf(m, __shfl_xor_sync(0xffffffffu, m, o));

        float psum = 0.f;
        float p[4];
#pragma unroll
        for (int jb = 0; jb < 4; jb++) {
            int j = jb * 32 + lane;
            p[jb] = (j < Kn) ? __expf(el[jb] - m) : 0.f;
            psum += p[jb];
        }
#pragma unroll
        for (int o = 16; o; o >>= 1) psum += __shfl_xor_sync(0xffffffffu, psum, o);
#pragma unroll
        for (int jb = 0; jb < 4; jb++) {
            int j = jb * 32 + lane;
            if (j < 128) prow[wid * 128 + j] = p[jb];
        }
        __syncwarp();
        const float rinv = 1.0f / psum;

        // attn @ x : lane owns f-quad [4*lane, 4*lane+3]
        float4 h = {0.f, 0.f, 0.f, 0.f};
        const float* xcol = xs + 4 * lane;
#pragma unroll 4
        for (int j = 0; j < Kn; j++) {
            float pj = prow[wid * 128 + j];
            float4 xv = *(const float4*)(xcol + j * Fn);
            h.x = fmaf(pj, xv.x, h.x);
            h.y = fmaf(pj, xv.y, h.y);
            h.z = fmaf(pj, xv.z, h.z);
            h.w = fmaf(pj, xv.w, h.w);
        }
        float4 o4;
        o4.x = 1.0f / (1.0f + __expf(-h.x * rinv));
        o4.y = 1.0f / (1.0f + __expf(-h.y * rinv));
        o4.z = 1.0f / (1.0f + __expf(-h.z * rinv));
        o4.w = 1.0f / (1.0f + __expf(-h.w * rinv));
        *(float4*)&out[(b * Kn + i) * Fn + 4 * lane] = o4;
    }
}

// ---------------------------------------------------------------------------
extern "C" void kernel_launch(void* const* d_in, const int* in_sizes, int n_in,
                              void* d_out, int out_size) {
    const float* x    = (const float*)d_in[0];
    const float* W    = (const float*)d_in[1];
    const float* bvec = (const float*)d_in[2];
    const float* avec = (const float*)d_in[3];
    const float* bias = (const float*)d_in[4];
    float* out = (float*)d_out;

    const size_t smem1 = (64 * 132 + 128 * 64) * sizeof(float);           // 66.5 KB
    const size_t smem2 = (128 * EPAD + Kn * Fn + 16 * EPAD + EPAD + EPAD
                          + 128 + 16 * 128) * sizeof(float);              // 179 KB

    cudaFuncSetAttribute(proj_kernel, cudaFuncAttributeMaxDynamicSharedMemorySize,
                         (int)smem1);
    cudaFuncSetAttribute(attn_kernel, cudaFuncAttributeMaxDynamicSharedMemorySize,
                         (int)smem2);

    proj_kernel<<<dim3(7, 100), 256, smem1>>>(x, W, bvec);
    attn_kernel<<<dim3(Bn, 7), 512, smem2>>>(x, avec, bias, out);
}

// round 2
// speedup vs baseline: 1.3666x; 1.3666x over previous
#include <cuda_runtime.h>

#define ALPHA 0.2f
constexpr int Bn = 64, Kn = 100, Fn = 128, En = 200, JP = 128;
constexpr int ROWS = Bn * Kn;          // 6400

// Scratch (no allocations allowed)
__device__ float g_UL[ROWS * En];      // left proj + lin-bias folded, row-major [row][e]
__device__ float g_RT[Bn * En * JP];   // right proj TRANSPOSED per batch: [b][e][j], j<100 valid

// ---------------------------------------------------------------------------
// Kernel 1: projection GEMM.  X:(6400,128) @ [W_top | W_bot]:(128,400)
// n < 200 -> g_UL[row][n] (+= b[n]);  n in [200,400) -> g_RT[b][n-200][row%100]
// ---------------------------------------------------------------------------
__global__ void proj_kernel(const float* __restrict__ x,
                            const float* __restrict__ W,
                            const float* __restrict__ bvec) {
    extern __shared__ float sm[];
    float(*xs)[132] = (float(*)[132])sm;               // 64 x 132 (padded)
    float(*ws)[64]  = (float(*)[64])(sm + 64 * 132);   // 128 x 64

    const int row0 = blockIdx.y * 64;
    const int n0   = blockIdx.x * 64;
    const int tid  = threadIdx.x;

    for (int idx = tid; idx < 64 * 128; idx += 256) {
        int r = idx >> 7, f = idx & 127;
        xs[r][f] = x[(row0 + r) * Fn + f];
    }
    for (int idx = tid; idx < 128 * 64; idx += 256) {
        int f = idx >> 6, c = idx & 63;
        int n = n0 + c;
        float v = 0.f;
        if (n < En)            v = W[f * En + n];
        else if (n < 2 * En)   v = W[(Fn + f) * En + (n - En)];
        ws[f][c] = v;
    }
    __syncthreads();

    const int tx = tid & 15, ty = tid >> 4;
    float acc[4][4] = {};
#pragma unroll 4
    for (int f = 0; f < 128; f++) {
        float4 wv = *(const float4*)&ws[f][4 * tx];
        float xr[4];
#pragma unroll
        for (int r = 0; r < 4; r++) xr[r] = xs[4 * ty + r][f];
#pragma unroll
        for (int r = 0; r < 4; r++) {
            acc[r][0] = fmaf(xr[r], wv.x, acc[r][0]);
            acc[r][1] = fmaf(xr[r], wv.y, acc[r][1]);
            acc[r][2] = fmaf(xr[r], wv.z, acc[r][2]);
            acc[r][3] = fmaf(xr[r], wv.w, acc[r][3]);
        }
    }
    const int nq = n0 + 4 * tx;
#pragma unroll
    for (int r = 0; r < 4; r++) {
        int row = row0 + 4 * ty + r;
        if (nq < En) {                       // whole quad < 200 (quads never straddle)
            float4 bv = *(const float4*)&bvec[nq];
            float4 st;
            st.x = acc[r][0] + bv.x; st.y = acc[r][1] + bv.y;
            st.z = acc[r][2] + bv.z; st.w = acc[r][3] + bv.w;
            *(float4*)&g_UL[row * En + nq] = st;
        } else {
            int bb = row / Kn, k = row - bb * Kn;
#pragma unroll
            for (int c = 0; c < 4; c++) {
                int n = nq + c;
                if (n < 2 * En)
                    g_RT[(bb * En + (n - En)) * JP + k] = acc[r][c];
            }
        }
    }
}

// ---------------------------------------------------------------------------
// Kernel 2: fused scores + softmax + attn@x + sigmoid.
// Block = (b, half of rows). Warp owns rows wid+16r. Lane owns j-quad 4*lane.
// e_ij = 0.25*(ua1_i + ra1_j) + sum_e max(u_ie+R_ej,0)*a1_e + bias_ij
//   where a1 = (1-alpha)*a, and alpha/(1-alpha) = 0.25.
// ---------------------------------------------------------------------------
template <int R>
__device__ __forceinline__ void do_rows(
    const float* R_sm, const float* xs, const float* u_sm, float* prow,
    const float* a1, const int* lrow, int base, int b, int lane,
    const float* __restrict__ bias, float* __restrict__ out) {

    const bool jv = (lane < 25);           // lane's j-quad 4l..4l+3 < 100

    // ua1_r = u_r . a1 (conflict-free strided LDS, warp reduce)
    float aua[R];
#pragma unroll
    for (int r = 0; r < R; r++) {
        float s = 0.f;
        const float* up = u_sm + lrow[r] * En;
        for (int e = lane; e < En; e += 32) s = fmaf(up[e], a1[e], s);
#pragma unroll
        for (int o = 16; o; o >>= 1) s += __shfl_xor_sync(0xffffffffu, s, o);
        aua[r] = 0.25f * s;
    }

    float4 bias4[R];
#pragma unroll
    for (int r = 0; r < R; r++) {
        float4 bv = {0.f, 0.f, 0.f, 0.f};
        if (jv) bv = *(const float4*)(bias + (base + lrow[r]) * Kn + 4 * lane);
        bias4[r] = bv;
    }

    // ---- scores: conflict-free, 4-row register-blocked ----
    float acc[R][4];
#pragma unroll
    for (int r = 0; r < R; r++)
        acc[r][0] = acc[r][1] = acc[r][2] = acc[r][3] = 0.f;
    float racc[4] = {0.f, 0.f, 0.f, 0.f};

    const float* rp = R_sm + 4 * lane;
#pragma unroll 2
    for (int e = 0; e < En; e++) {
        float4 r4 = *(const float4*)(rp + e * JP);   // LDS.128 conflict-free
        float av = a1[e];                            // broadcast
        racc[0] = fmaf(r4.x, av, racc[0]);
        racc[1] = fmaf(r4.y, av, racc[1]);
        racc[2] = fmaf(r4.z, av, racc[2]);
        racc[3] = fmaf(r4.w, av, racc[3]);
#pragma unroll
        for (int r = 0; r < R; r++) {
            float ur = u_sm[lrow[r] * En + e];       // broadcast
            acc[r][0] = fmaf(fmaxf(ur + r4.x, 0.f), av, acc[r][0]);
            acc[r][1] = fmaf(fmaxf(ur + r4.y, 0.f), av, acc[r][1]);
            acc[r][2] = fmaf(fmaxf(ur + r4.z, 0.f), av, acc[r][2]);
            acc[r][3] = fmaf(fmaxf(ur + r4.w, 0.f), av, acc[r][3]);
        }
    }

    // ---- softmax per row (unnormalized p -> prow, keep 1/sum in regs) ----
    float rinv[R];
#pragma unroll
    for (int r = 0; r < R; r++) {
        float el[4];
        el[0] = jv ? (aua[r] + 0.25f * racc[0] + acc[r][0] + bias4[r].x) : -1e30f;
        el[1] = jv ? (aua[r] + 0.25f * racc[1] + acc[r][1] + bias4[r].y) : -1e30f;
        el[2] = jv ? (aua[r] + 0.25f * racc[2] + acc[r][2] + bias4[r].z) : -1e30f;
        el[3] = jv ? (aua[r] + 0.25f * racc[3] + acc[r][3] + bias4[r].w) : -1e30f;
        float m = fmaxf(fmaxf(el[0], el[1]), fmaxf(el[2], el[3]));
#pragma unroll
        for (int o = 16; o; o >>= 1) m = fmaxf(m, __shfl_xor_sync(0xffffffffu, m, o));
        float4 p;
        p.x = jv ? __expf(el[0] - m) : 0.f;
        p.y = jv ? __expf(el[1] - m) : 0.f;
        p.z = jv ? __expf(el[2] - m) : 0.f;
        p.w = jv ? __expf(el[3] - m) : 0.f;
        float ps = p.x + p.y + p.z + p.w;
#pragma unroll
        for (int o = 16; o; o >>= 1) ps += __shfl_xor_sync(0xffffffffu, ps, o);
        if (jv) *(float4*)(prow + lrow[r] * JP + 4 * lane) = p;
        rinv[r] = 1.0f / ps;
    }
    __syncwarp();

    // ---- attn @ x : lane owns f-quad, R rows share each x row ----
    float4 h[R];
#pragma unroll
    for (int r = 0; r < R; r++) h[r] = make_float4(0.f, 0.f, 0.f, 0.f);
    const float* xc = xs + 4 * lane;
#pragma unroll 4
    for (int j = 0; j < Kn; j++) {
        float4 xv = *(const float4*)(xc + j * Fn);
#pragma unroll
        for (int r = 0; r < R; r++) {
            float pj = prow[lrow[r] * JP + j];
            h[r].x = fmaf(pj, xv.x, h[r].x);
            h[r].y = fmaf(pj, xv.y, h[r].y);
            h[r].z = fmaf(pj, xv.z, h[r].z);
            h[r].w = fmaf(pj, xv.w, h[r].w);
        }
    }
#pragma unroll
    for (int r = 0; r < R; r++) {
        int i = base + lrow[r];
        float ri = rinv[r];
        float4 o4;
        o4.x = 1.0f / (1.0f + __expf(-h[r].x * ri));
        o4.y = 1.0f / (1.0f + __expf(-h[r].y * ri));
        o4.z = 1.0f / (1.0f + __expf(-h[r].z * ri));
        o4.w = 1.0f / (1.0f + __expf(-h[r].w * ri));
        *(float4*)(out + (b * Kn + i) * Fn + 4 * lane) = o4;
    }
}

__global__ __launch_bounds__(512, 1)
void attn_kernel(const float* __restrict__ x,
                 const float* __restrict__ avec,
                 const float* __restrict__ bias,
                 float* __restrict__ out) {
    extern __shared__ float sm[];
    float* R_sm = sm;                    // En*JP   = 25600 f
    float* xs   = R_sm + En * JP;        // Kn*Fn   = 12800 f
    float* u_sm = xs + Kn * Fn;          // 52*En   = 10400 f
    float* prow = u_sm + 52 * En;        // 52*JP   =  6656 f
    float* a1   = prow + 52 * JP;        // En      =   200 f

    const int b     = blockIdx.x;
    const int base  = blockIdx.y ? 52 : 0;
    const int nrows = blockIdx.y ? 48 : 52;
    const int tid   = threadIdx.x;
    const int wid   = tid >> 5, lane = tid & 31;

    // ---- staging (all vectorized, coalesced) ----
    {
        const float4* src = (const float4*)(g_RT + b * En * JP);
        float4* dst = (float4*)R_sm;
        const float4 z4 = {0.f, 0.f, 0.f, 0.f};
        for (int idx = tid; idx < En * (JP / 4); idx += 512) {
            int q = idx & 31;
            dst[idx] = (q < 25) ? src[idx] : z4;   // zero-pad j in [100,128)
        }
    }
    {
        const float4* src = (const float4*)(x + b * Kn * Fn);
        float4* dst = (float4*)xs;
        for (int idx = tid; idx < Kn * Fn / 4; idx += 512) dst[idx] = src[idx];
    }
    {
        const float4* src = (const float4*)(g_UL + (b * Kn + base) * En);
        float4* dst = (float4*)u_sm;
        for (int idx = tid; idx < nrows * En / 4; idx += 512) dst[idx] = src[idx];
    }
    for (int e = tid; e < En; e += 512) a1[e] = (1.0f - ALPHA) * avec[e];
    __syncthreads();

    int lrow[4], R = 0;
#pragma unroll
    for (int r = 0; r < 4; r++) {
        int lr = wid + 16 * r;
        if (lr < nrows) lrow[R++] = lr;
    }
    if (R == 4) do_rows<4>(R_sm, xs, u_sm, prow, a1, lrow, base, b, lane, bias, out);
    else        do_rows<3>(R_sm, xs, u_sm, prow, a1, lrow, base, b, lane, bias, out);
}

// ---------------------------------------------------------------------------
extern "C" void kernel_launch(void* const* d_in, const int* in_sizes, int n_in,
                              void* d_out, int out_size) {
    const float* x    = (const float*)d_in[0];
    const float* W    = (const float*)d_in[1];
    const float* bvec = (const float*)d_in[2];
    const float* avec = (const float*)d_in[3];
    const float* bias = (const float*)d_in[4];
    float* out = (float*)d_out;

    const size_t smem1 = (64 * 132 + 128 * 64) * sizeof(float);            // 66.5 KB
    const size_t smem2 = (En * JP + Kn * Fn + 52 * En + 52 * JP + En)
                         * sizeof(float);                                   // ~217.4 KB

    cudaFuncSetAttribute(proj_kernel, cudaFuncAttributeMaxDynamicSharedMemorySize,
                         (int)smem1);
    cudaFuncSetAttribute(attn_kernel, cudaFuncAttributeMaxDynamicSharedMemorySize,
                         (int)smem2);

    proj_kernel<<<dim3(7, 100), 256, smem1>>>(x, W, bvec);
    attn_kernel<<<dim3(Bn, 2), 512, smem2>>>(x, avec, bias, out);
}

// round 4
// speedup vs baseline: 1.4365x; 1.0511x over previous
#include <cuda_runtime.h>

#define ALPHA 0.2f
constexpr int Bn = 64, Kn = 100, Fn = 128, En = 200, JP = 128;
constexpr int ROWS = Bn * Kn;          // 6400

// Scratch (no allocations allowed)
__device__ float g_UL[ROWS * En];      // left proj + lin-bias folded, [row][e]
__device__ float g_RT[Bn * En * JP];   // right proj transposed per batch: [b][e][j]

// ---------------------------------------------------------------------------
// Kernel 1: projection GEMM.  X:(6400,128) @ [W_top | W_bot]:(128,400)
// n < 200 -> g_UL[row][n] (+= b[n]);  n in [200,400) -> g_RT[b][n-200][row%100]
// R-tiles are transposed through smem so the g_RT store is coalesced.
// ---------------------------------------------------------------------------
__global__ void proj_kernel(const float* __restrict__ x,
                            const float* __restrict__ W,
                            const float* __restrict__ bvec) {
    extern __shared__ float sm[];
    float(*xs)[132]   = (float(*)[132])sm;                     // 64 x 132
    float(*ws)[64]    = (float(*)[64])(sm + 64 * 132);         // 128 x 64
    float(*trbuf)[65] = (float(*)[65])(sm + 64 * 132 + 128 * 64); // 64 x 65

    const int row0 = blockIdx.y * 64;
    const int n0   = blockIdx.x * 64;
    const int tid  = threadIdx.x;

    for (int idx = tid; idx < 64 * (128 / 4); idx += 256) {
        int r = idx >> 5, fq = idx & 31;
        *(float4*)&xs[r][4 * fq] = *(const float4*)&x[(row0 + r) * Fn + 4 * fq];
    }
    for (int idx = tid; idx < 128 * 64; idx += 256) {
        int f = idx >> 6, c = idx & 63;
        int n = n0 + c;
        float v = 0.f;
        if (n < En)            v = W[f * En + n];
        else if (n < 2 * En)   v = W[(Fn + f) * En + (n - En)];
        ws[f][c] = v;
    }
    __syncthreads();

    const int tx = tid & 15, ty = tid >> 4;
    float acc[4][4] = {};
#pragma unroll
    for (int f0 = 0; f0 < 128; f0 += 4) {
        float4 xr4[4];
#pragma unroll
        for (int r = 0; r < 4; r++)
            xr4[r] = *(const float4*)&xs[4 * ty + r][f0];
#pragma unroll
        for (int ff = 0; ff < 4; ff++) {
            float4 wv = *(const float4*)&ws[f0 + ff][4 * tx];
#pragma unroll
            for (int r = 0; r < 4; r++) {
                float xv = (ff == 0) ? xr4[r].x : (ff == 1) ? xr4[r].y
                         : (ff == 2) ? xr4[r].z : xr4[r].w;
                acc[r][0] = fmaf(xv, wv.x, acc[r][0]);
                acc[r][1] = fmaf(xv, wv.y, acc[r][1]);
                acc[r][2] = fmaf(xv, wv.z, acc[r][2]);
                acc[r][3] = fmaf(xv, wv.w, acc[r][3]);
            }
        }
    }

    const int nq = n0 + 4 * tx;
    if (nq < En) {                          // UL quad (quads never straddle 200)
        float4 bv = *(const float4*)&bvec[nq];
#pragma unroll
        for (int r = 0; r < 4; r++) {
            int row = row0 + 4 * ty + r;
            float4 st;
            st.x = acc[r][0] + bv.x; st.y = acc[r][1] + bv.y;
            st.z = acc[r][2] + bv.z; st.w = acc[r][3] + bv.w;
            *(float4*)&g_UL[row * En + nq] = st;
        }
    } else {                                // R quad -> smem transpose buffer
#pragma unroll
        for (int r = 0; r < 4; r++)
#pragma unroll
            for (int c = 0; c < 4; c++)
                trbuf[4 * tx + c][4 * ty + r] = acc[r][c];
    }

    if (n0 + 63 >= En) {                    // block holds R columns
        __syncthreads();
        for (int idx = tid; idx < 64 * 64; idx += 256) {
            int e_l = idx >> 6, k_l = idx & 63;
            int n = n0 + e_l;
            if (n >= En && n < 2 * En) {    // <-- restored upper guard (R3 bug)
                int row = row0 + k_l;
                int bb = row / Kn, k = row - bb * Kn;
                g_RT[(bb * En + (n - En)) * JP + k] = trbuf[e_l][k_l];
            }
        }
    }
}

// ---------------------------------------------------------------------------
// Kernel 2: fused scores + softmax + attn@x + sigmoid.
// leaky(z) = 0.6 z + 0.4 |z|  (exact for alpha = 0.2), so
// e_ij = 1.5*(ua04_i + ra04_j) + sum_e a04_e * |u_ie + R_ej| + bias_ij,
// with a04 = 0.4*a,  ua04 = u.a04,  ra04 = R_j.a04.
// Block = (b, half of rows). Warp owns rows wid+16r. Lane owns j-quad 4*lane.
// ---------------------------------------------------------------------------
template <int R>
__device__ __forceinline__ void do_rows(
    const float* R_sm, const float* xs, const float* u_sm, float* prow,
    const float* a04, const float* ra_sm, const int* lrow, int base, int b,
    int lane, const float* __restrict__ bias, float* __restrict__ out) {

    const bool jv = (lane < 25);            // lane's j-quad 4l..4l+3 < 100

    // ua15_r = 1.5 * (u_r . a04)  (conflict-free strided LDS, warp reduce)
    float aua[R];
#pragma unroll
    for (int r = 0; r < R; r++) {
        float s = 0.f;
        const float* up = u_sm + lrow[r] * En;
        for (int e = lane; e < En; e += 32) s = fmaf(up[e], a04[e], s);
#pragma unroll
        for (int o = 16; o; o >>= 1) s += __shfl_xor_sync(0xffffffffu, s, o);
        aua[r] = 1.5f * s;
    }

    float4 bias4[R];
#pragma unroll
    for (int r = 0; r < R; r++) {
        float4 bv = {0.f, 0.f, 0.f, 0.f};
        if (jv) bv = *(const float4*)(bias + (base + lrow[r]) * Kn + 4 * lane);
        bias4[r] = bv;
    }
    float4 ra4 = *(const float4*)(ra_sm + 4 * lane);   // 1.5 * ra04, j-quad

    // ---- scores: 2 fma-pipe ops per element, |z| as free FFMA modifier ----
    float acc[R][4];
#pragma unroll
    for (int r = 0; r < R; r++)
        acc[r][0] = acc[r][1] = acc[r][2] = acc[r][3] = 0.f;

    const float* rp = R_sm + 4 * lane;
#pragma unroll 2
    for (int e = 0; e < En; e++) {
        float4 r4 = *(const float4*)(rp + e * JP);     // LDS.128 conflict-free
        float av = a04[e];                             // broadcast
#pragma unroll
        for (int r = 0; r < R; r++) {
            float ur = u_sm[lrow[r] * En + e];         // broadcast
            acc[r][0] = fmaf(fabsf(ur + r4.x), av, acc[r][0]);
            acc[r][1] = fmaf(fabsf(ur + r4.y), av, acc[r][1]);
            acc[r][2] = fmaf(fabsf(ur + r4.z), av, acc[r][2]);
            acc[r][3] = fmaf(fabsf(ur + r4.w), av, acc[r][3]);
        }
    }

    // ---- softmax per row (unnormalized p -> prow, keep 1/sum in regs) ----
    float rinv[R];
#pragma unroll
    for (int r = 0; r < R; r++) {
        float el[4];
        el[0] = jv ? (aua[r] + ra4.x + acc[r][0] + bias4[r].x) : -1e30f;
        el[1] = jv ? (aua[r] + ra4.y + acc[r][1] + bias4[r].y) : -1e30f;
        el[2] = jv ? (aua[r] + ra4.z + acc[r][2] + bias4[r].z) : -1e30f;
        el[3] = jv ? (aua[r] + ra4.w + acc[r][3] + bias4[r].w) : -1e30f;
        float m = fmaxf(fmaxf(el[0], el[1]), fmaxf(el[2], el[3]));
#pragma unroll
        for (int o = 16; o; o >>= 1) m = fmaxf(m, __shfl_xor_sync(0xffffffffu, m, o));
        float4 p;
        p.x = jv ? __expf(el[0] - m) : 0.f;
        p.y = jv ? __expf(el[1] - m) : 0.f;
        p.z = jv ? __expf(el[2] - m) : 0.f;
        p.w = jv ? __expf(el[3] - m) : 0.f;
        float ps = p.x + p.y + p.z + p.w;
#pragma unroll
        for (int o = 16; o; o >>= 1) ps += __shfl_xor_sync(0xffffffffu, ps, o);
        if (jv) *(float4*)(prow + lrow[r] * JP + 4 * lane) = p;
        rinv[r] = 1.0f / ps;
    }
    __syncwarp();

    // ---- attn @ x : lane owns f-quad; p loaded as float4 per 4 j ----
    float4 h[R];
#pragma unroll
    for (int r = 0; r < R; r++) h[r] = make_float4(0.f, 0.f, 0.f, 0.f);
    const float* xc = xs + 4 * lane;
#pragma unroll 5
    for (int jq = 0; jq < Kn / 4; jq++) {
        float4 p4[R];
#pragma unroll
        for (int r = 0; r < R; r++)
            p4[r] = *(const float4*)(prow + lrow[r] * JP + 4 * jq);
#pragma unroll
        for (int c = 0; c < 4; c++) {
            float4 xv = *(const float4*)(xc + (4 * jq + c) * Fn);
#pragma unroll
            for (int r = 0; r < R; r++) {
                float pj = (c == 0) ? p4[r].x : (c == 1) ? p4[r].y
                         : (c == 2) ? p4[r].z : p4[r].w;
                h[r].x = fmaf(pj, xv.x, h[r].x);
                h[r].y = fmaf(pj, xv.y, h[r].y);
                h[r].z = fmaf(pj, xv.z, h[r].z);
                h[r].w = fmaf(pj, xv.w, h[r].w);
            }
        }
    }
#pragma unroll
    for (int r = 0; r < R; r++) {
        int i = base + lrow[r];
        float ri = rinv[r];
        float4 o4;
        o4.x = 1.0f / (1.0f + __expf(-h[r].x * ri));
        o4.y = 1.0f / (1.0f + __expf(-h[r].y * ri));
        o4.z = 1.0f / (1.0f + __expf(-h[r].z * ri));
        o4.w = 1.0f / (1.0f + __expf(-h[r].w * ri));
        *(float4*)(out + (b * Kn + i) * Fn + 4 * lane) = o4;
    }
}

__global__ __launch_bounds__(512, 1)
void attn_kernel(const float* __restrict__ x,
                 const float* __restrict__ avec,
                 const float* __restrict__ bias,
                 float* __restrict__ out) {
    extern __shared__ float sm[];
    float* R_sm  = sm;                    // En*JP   = 25600 f
    float* xs    = R_sm + En * JP;        // Kn*Fn   = 12800 f
    float* u_sm  = xs + Kn * Fn;          // 52*En   = 10400 f
    float* prow  = u_sm + 52 * En;        // 52*JP   =  6656 f
    float* a04   = prow + 52 * JP;        // En      =   200 f
    float* ra_sm = a04 + En;              // JP      =   128 f

    const int b     = blockIdx.x;
    const int base  = blockIdx.y ? 52 : 0;
    const int nrows = blockIdx.y ? 48 : 52;
    const int tid   = threadIdx.x;
    const int wid   = tid >> 5, lane = tid & 31;

    // ---- staging (vectorized, coalesced) ----
    {
        const float4* src = (const float4*)(g_RT + b * En * JP);
        float4* dst = (float4*)R_sm;
        const float4 z4 = {0.f, 0.f, 0.f, 0.f};
        for (int idx = tid; idx < En * (JP / 4); idx += 512) {
            int q = idx & 31;
            dst[idx] = (q < 25) ? src[idx] : z4;   // zero-pad j in [100,128)
        }
    }
    {
        const float4* src = (const float4*)(x + b * Kn * Fn);
        float4* dst = (float4*)xs;
        for (int idx = tid; idx < Kn * Fn / 4; idx += 512) dst[idx] = src[idx];
    }
    {
        const float4* src = (const float4*)(g_UL + (b * Kn + base) * En);
        float4* dst = (float4*)u_sm;
        for (int idx = tid; idx < nrows * En / 4; idx += 512) dst[idx] = src[idx];
    }
    for (int e = tid; e < En; e += 512) a04[e] = 0.4f * avec[e];
    __syncthreads();

    // ---- ra_sm[j] = 1.5 * (R_j . a04), warps 0-3, lanes own consecutive j ----
    if (wid < 4) {
        int j = wid * 32 + lane;
        float s = 0.f;
        const float* rc = R_sm + j;
        for (int e = 0; e < En; e++) s = fmaf(rc[e * JP], a04[e], s);
        ra_sm[j] = 1.5f * s;
    }
    __syncthreads();

    int lrow[4], R = 0;
#pragma unroll
    for (int r = 0; r < 4; r++) {
        int lr = wid + 16 * r;
        if (lr < nrows) lrow[R++] = lr;
    }
    if (R == 4) do_rows<4>(R_sm, xs, u_sm, prow, a04, ra_sm, lrow, base, b, lane, bias, out);
    else        do_rows<3>(R_sm, xs, u_sm, prow, a04, ra_sm, lrow, base, b, lane, bias, out);
}

// ---------------------------------------------------------------------------
extern "C" void kernel_launch(void* const* d_in, const int* in_sizes, int n_in,
                              void* d_out, int out_size) {
    const float* x    = (const float*)d_in[0];
    const float* W    = (const float*)d_in[1];
    const float* bvec = (const float*)d_in[2];
    const float* avec = (const float*)d_in[3];
    const float* bias = (const float*)d_in[4];
    float* out = (float*)d_out;

    const size_t smem1 = (64 * 132 + 128 * 64 + 64 * 65) * sizeof(float);  // ~83 KB
    const size_t smem2 = (En * JP + Kn * Fn + 52 * En + 52 * JP + En + JP)
                         * sizeof(float);                                   // ~223.7 KB

    cudaFuncSetAttribute(proj_kernel, cudaFuncAttributeMaxDynamicSharedMemorySize,
                         (int)smem1);
    cudaFuncSetAttribute(attn_kernel, cudaFuncAttributeMaxDynamicSharedMemorySize,
                         (int)smem2);

    proj_kernel<<<dim3(7, 100), 256, smem1>>>(x, W, bvec);
    attn_kernel<<<dim3(Bn, 2), 512, smem2>>>(x, avec, bias, out);
}